// round 13
// baseline (speedup 1.0000x reference)
#include <cuda_runtime.h>
#include <cstdint>

#define B_      16
#define N_      131072
#define NP_     2048
#define BPB     8                    // blocks per batch = cluster size
#define THREADS 512
#define CHUNK   (N_ / BPB)           // 16384 points per CTA
#define PAIRS   (CHUNK / THREADS / 2) // 16 float2-pairs per thread
#define SMEM_BYTES (3 * CHUNK * 4)   // 192 KB SoA xyz

// ---------- packed f32x2 helpers (exactly-rounded per lane == scalar fp32) ----------
__device__ __forceinline__ unsigned long long pk2(float lo, float hi) {
    unsigned long long r;
    asm("mov.b64 %0, {%1, %2};" : "=l"(r) : "f"(lo), "f"(hi));
    return r;
}
__device__ __forceinline__ void up2(unsigned long long v, float& lo, float& hi) {
    asm("mov.b64 {%0, %1}, %2;" : "=f"(lo), "=f"(hi) : "l"(v));
}
__device__ __forceinline__ unsigned long long f2add(unsigned long long a, unsigned long long b) {
    unsigned long long c;
    asm("add.rn.f32x2 %0, %1, %2;" : "=l"(c) : "l"(a), "l"(b));
    return c;
}
__device__ __forceinline__ unsigned long long f2mul(unsigned long long a, unsigned long long b) {
    unsigned long long c;
    asm("mul.rn.f32x2 %0, %1, %2;" : "=l"(c) : "l"(a), "l"(b));
    return c;
}

// ---------- DSMEM helpers ----------
__device__ __forceinline__ unsigned smem_u32(const void* p) {
    return (unsigned)__cvta_generic_to_shared(p);
}
__device__ __forceinline__ unsigned mapa_rank(unsigned laddr, unsigned rk) {
    unsigned r;
    asm("mapa.shared::cluster.u32 %0, %1, %2;" : "=r"(r) : "r"(laddr), "r"(rk));
    return r;
}
__device__ __forceinline__ void stc_u64(unsigned a, unsigned long long v) {
    asm volatile("st.shared::cluster.u64 [%0], %1;" :: "r"(a), "l"(v) : "memory");
}
__device__ __forceinline__ void stc_f32(unsigned a, float v) {
    asm volatile("st.shared::cluster.f32 [%0], %1;" :: "r"(a), "f"(v) : "memory");
}

extern __shared__ float smem[];  // [3*CHUNK] SoA: x | y | z

__global__ void __launch_bounds__(THREADS, 1) __cluster_dims__(BPB, 1, 1)
fps_kernel(const float* __restrict__ xyz,
           const int*  __restrict__ finit,   // int32 (verified by R11 diagnostics)
           float*      __restrict__ out)     // float32 output (checker reads f32)
{
    // cluster-combine slots, double-buffered by step parity
    __shared__ unsigned long long sKey[2][BPB];
    __shared__ float sCx[2][BPB], sCy[2][BPB], sCz[2][BPB];
    __shared__ float wv[THREADS / 32];
    __shared__ unsigned wi[THREADS / 32];

    const int t    = threadIdx.x;
    const int blk  = blockIdx.x;
    const int b    = blk / BPB;
    const int rank = blk % BPB;
    const int lane = t & 31;
    const int warp = t >> 5;

    float* sx = smem;
    float* sy = smem + CHUNK;
    float* sz = smem + 2 * CHUNK;

    const float* xb = xyz + (size_t)b * N_ * 3;

    // ---- one-time: load this CTA's chunk [rank*CHUNK, +CHUNK) into SMEM SoA ----
    {
        const float* src = xb + (size_t)rank * CHUNK * 3;
        for (int i = t; i < CHUNK * 3; i += THREADS) {
            float v = src[i];
            int p = i / 3;
            int c = i - p * 3;
            if (c == 0) sx[p] = v;
            else if (c == 1) sy[p] = v;
            else sz[p] = v;
        }
    }
    __syncthreads();

    // initial centroid from farthest_init (int32; mask for memory safety)
    unsigned cur = (unsigned)finit[b];
    if (cur >= (unsigned)N_) cur %= (unsigned)N_;
    float cx = xb[(size_t)cur * 3 + 0];
    float cy = xb[(size_t)cur * 3 + 1];
    float cz = xb[(size_t)cur * 3 + 2];

    // register-resident min distances (init = 1e10 per reference; re-init each
    // launch -> graph-replay deterministic)
    float dist[2 * PAIRS];
#pragma unroll
    for (int i = 0; i < 2 * PAIRS; i++) dist[i] = 1e10f;

    for (int s = 0;; ++s) {
        // reference emits the incoming carry each step; output as float32
        if (rank == 0 && t == 0) out[(size_t)b * NP_ + s] = (float)cur;
        if (s == NP_ - 1) break;

        // negated centroid, packed (x - c == x + (-c), IEEE-exact)
        const unsigned long long ncx = pk2(-cx, -cx);
        const unsigned long long ncy = pk2(-cy, -cy);
        const unsigned long long ncz = pk2(-cz, -cz);

        float bv = -1.0f;
        unsigned bi = 0;
#pragma unroll
        for (int j = 0; j < PAIRS; j++) {
            const int l = j * (2 * THREADS) + 2 * t;  // even -> 8B aligned
            float2 xv = *reinterpret_cast<const float2*>(sx + l);
            float2 yv = *reinterpret_cast<const float2*>(sy + l);
            float2 zv = *reinterpret_cast<const float2*>(sz + l);
            unsigned long long dx = f2add(pk2(xv.x, xv.y), ncx);
            unsigned long long dy = f2add(pk2(yv.x, yv.y), ncy);
            unsigned long long dz = f2add(pk2(zv.x, zv.y), ncz);
            // XLA order: (dx^2 + dy^2) + dz^2, no FMA contraction
            unsigned long long ss = f2add(f2add(f2mul(dx, dx), f2mul(dy, dy)), f2mul(dz, dz));
            float s0, s1;
            up2(ss, s0, s1);
            float m0 = fminf(dist[2 * j], s0);
            dist[2 * j] = m0;
            if (m0 > bv) { bv = m0; bi = (unsigned)l; }       // strict > keeps first index
            float m1 = fminf(dist[2 * j + 1], s1);
            dist[2 * j + 1] = m1;
            if (m1 > bv) { bv = m1; bi = (unsigned)l + 1; }
        }

        // ---- warp reduce: lexicographic max(value), tie -> min(index) ----
#pragma unroll
        for (int off = 16; off; off >>= 1) {
            float    ov = __shfl_down_sync(0xFFFFFFFFu, bv, off);
            unsigned oi = __shfl_down_sync(0xFFFFFFFFu, bi, off);
            if (ov > bv || (ov == bv && oi < bi)) { bv = ov; bi = oi; }
        }
        if (lane == 0) { wv[warp] = bv; wi[warp] = bi; }
        __syncthreads();

        // ---- warp 0 reduces the 16 warp bests; lane 0 publishes to all cluster peers ----
        if (warp == 0) {
            float    v2 = (lane < THREADS / 32) ? wv[lane] : -1.0f;
            unsigned i2 = (lane < THREADS / 32) ? wi[lane] : 0xFFFFFFFFu;
#pragma unroll
            for (int off = 8; off; off >>= 1) {
                float    ov = __shfl_down_sync(0xFFFFFFFFu, v2, off);
                unsigned oi = __shfl_down_sync(0xFFFFFFFFu, i2, off);
                if (ov > v2 || (ov == v2 && oi < i2)) { v2 = ov; i2 = oi; }
            }
            if (lane == 0) {
                float x = sx[i2], y = sy[i2], z = sz[i2];
                unsigned g = (unsigned)(rank * CHUNK) + i2;          // batch-global index
                // key: value bits (non-neg fp32 -> order-preserving) high, ~idx low
                unsigned long long key =
                    ((unsigned long long)__float_as_uint(v2) << 32) | (unsigned)(~g);
                const int pp = s & 1;
                unsigned aK = smem_u32(&sKey[pp][rank]);
                unsigned aX = smem_u32(&sCx[pp][rank]);
                unsigned aY = smem_u32(&sCy[pp][rank]);
                unsigned aZ = smem_u32(&sCz[pp][rank]);
#pragma unroll
                for (unsigned rk = 0; rk < BPB; ++rk) {
                    stc_u64(mapa_rank(aK, rk), key);
                    stc_f32(mapa_rank(aX, rk), x);
                    stc_f32(mapa_rank(aY, rk), y);
                    stc_f32(mapa_rank(aZ, rk), z);
                }
            }
        }

        // cluster barrier: arrive(release) / wait(acquire) orders the DSMEM stores
        asm volatile("barrier.cluster.arrive.aligned;" ::: "memory");
        asm volatile("barrier.cluster.wait.aligned;" ::: "memory");

        // every thread reduces the 8 slots identically (broadcast LDS, conflict-free)
        const int pp = s & 1;
        unsigned long long kb = 0;
        int br = 0;
#pragma unroll
        for (int r = 0; r < BPB; r++) {
            unsigned long long k = sKey[pp][r];
            if (k > kb) { kb = k; br = r; }
        }
        cur = ~(unsigned)kb;
        cx = sCx[pp][br];
        cy = sCy[pp][br];
        cz = sCz[pp][br];
    }
}

extern "C" void kernel_launch(void* const* d_in, const int* in_sizes, int n_in,
                              void* d_out, int out_size)
{
    // Verified by R11 diagnostics: d_in[0]=xyz f32 [16,131072,3],
    // d_in[1]=farthest_init i32 [16], d_in[2]=npoints i32 [1].
    // Robust identification kept anyway:
    int xi = 0;
    for (int i = 1; i < n_in; i++)
        if (in_sizes[i] > in_sizes[xi]) xi = i;
    int fi = -1;
    for (int i = 0; i < n_in; i++)
        if (i != xi && in_sizes[i] > 1 && (fi < 0 || in_sizes[i] < in_sizes[fi])) fi = i;
    if (fi < 0) fi = (xi == 0 && n_in > 1) ? 1 : 0;

    cudaFuncSetAttribute(fps_kernel, cudaFuncAttributeMaxDynamicSharedMemorySize, SMEM_BYTES);
    fps_kernel<<<B_ * BPB, THREADS, SMEM_BYTES>>>(
        (const float*)d_in[xi], (const int*)d_in[fi], (float*)d_out);
}